// round 16
// baseline (speedup 1.0000x reference)
#include <cuda_runtime.h>
#include <cuda_fp16.h>
#include <cstdint>
#include <math.h>

#define Bdim 4
#define Sdim 2048
#define Ddim 512
#define Hdim 8

// half scratch (device globals: allocation-free)
__device__ __half g_x [(size_t)Bdim * Sdim * Ddim];
__device__ __half g_wq[(size_t)Hdim * Ddim * Ddim];
__device__ __half g_wk[(size_t)Hdim * Ddim * Ddim];
__device__ __half g_wv[(size_t)Hdim * Ddim * Ddim];
__device__ __half g_wp[(size_t)Ddim * Hdim * Ddim];
__device__ __half g_q [(size_t)Bdim * Hdim * Sdim * Ddim];   // [b][h][s][e]
__device__ __half g_k [(size_t)Bdim * Hdim * Sdim * Ddim];   // [b][h][t][e]
__device__ __half g_v [(size_t)Bdim * Hdim * Sdim * Ddim];   // V^T: [b][h][e][t]
__device__ __half g_p [(size_t)Bdim * Hdim * Sdim * Sdim];   // exp(logit-4), unnormalized
__device__ __half g_c [(size_t)Bdim * Sdim * Hdim * Ddim];   // concat
__device__ float  g_rs[(size_t)Bdim * Hdim * Sdim];          // row sums

#define EXP_SHIFT 4.0f
#define LOG2E 1.4426950408889634f

// ---------------- fp16 mma.sync GEMM core (all-NT, fp32 accum) ----------------
// CTA 128x128, 256 threads (8 warps, 4x2), warp tile 32x64.
// K-chunk 64 halves, 3-stage cp.async pipeline, XOR-16B swizzle,
// ldmatrix.x4, m16n8k16 fp32-acc. 16 warps/SM at 2 CTAs/SM (RF-limited).
// ALL outputs (half and float) go through smem-transposed coalesced epilogues.
// EPI: 0 = plain, 1 = masked exp2 + row-sum atomics, 2 = rowsum normalize.

#define BUFS   32768                       // A tile 16KB + B tile 16KB
#define SM_TOTAL (3 * BUFS)                // 98304 bytes
#define EPITCH 68                          // half-stage pitch in uints (272B/row)
#define FPITCH 132                         // float-stage pitch in floats (528B/row)

__device__ __forceinline__ uint32_t smem_u32(const void* p) {
    uint32_t a;
    asm("{ .reg .u64 t; cvta.to.shared.u64 t, %1; cvt.u32.u64 %0, t; }"
        : "=r"(a) : "l"(p));
    return a;
}

__device__ __forceinline__ void cpasync16(uint32_t dst, const void* src) {
    asm volatile("cp.async.cg.shared.global [%0], [%1], 16;"
                 :: "r"(dst), "l"(src) : "memory");
}

__device__ __forceinline__ void mma16(float* c, const uint32_t* a,
                                      uint32_t b0, uint32_t b1) {
    asm volatile(
        "mma.sync.aligned.m16n8k16.row.col.f32.f16.f16.f32 "
        "{%0,%1,%2,%3}, {%4,%5,%6,%7}, {%8,%9}, {%0,%1,%2,%3};\n"
        : "+f"(c[0]), "+f"(c[1]), "+f"(c[2]), "+f"(c[3])
        : "r"(a[0]), "r"(a[1]), "r"(a[2]), "r"(a[3]), "r"(b0), "r"(b1));
}

__device__ __forceinline__ void ldm_x4(uint32_t* r, uint32_t addr) {
    asm volatile(
        "ldmatrix.sync.aligned.m8n8.x4.shared.b16 {%0,%1,%2,%3}, [%4];"
        : "=r"(r[0]), "=r"(r[1]), "=r"(r[2]), "=r"(r[3]) : "r"(addr));
}

__device__ __forceinline__ float ex2(float x) {
    float r;
    asm("ex2.approx.f32 %0, %1;" : "=f"(r) : "f"(x));
    return r;
}

__device__ __forceinline__ uint32_t pack2(float v0, float v1) {
    __half2 h = __floats2half2_rn(v0, v1);
    return *(uint32_t*)&h;
}

// stage one 128row x 64half tile via 4 cp.async.16B per thread (256 thr)
__device__ __forceinline__ void stage_cp(uint32_t sbuf, const __half* __restrict__ g,
                                         long ld, int kofs, int tid) {
#pragma unroll
    for (int i = 0; i < 4; i++) {
        const int idx = tid + i * 256;
        const int m = idx >> 3, ch = idx & 7;
        const int sc = ch ^ (m & 7);
        cpasync16(sbuf + (uint32_t)(m * 128 + sc * 16),
                  g + (long)m * ld + kofs + ch * 8);
    }
}

// cooperative coalesced flush of the 128x128-half stage -> global
__device__ __forceinline__ void flush_stage_h(const uint32_t* __restrict__ st,
                                              __half* __restrict__ C,
                                              int bm, int bn, int ldc,
                                              int wid, int lane)
{
#pragma unroll
    for (int i = 0; i < 8; i++) {
        const int row = i * 16 + wid * 2 + (lane >> 4);
        const int l16 = lane & 15;
        uint4 v = *(const uint4*)&st[row * EPITCH + l16 * 4];
        *(uint4*)&C[(long)(bm + row) * ldc + bn + l16 * 8] = v;
    }
}

// cooperative coalesced flush of the 128x128-float stage -> global
// each warp stores one full 512B row per iteration (32 lanes x float4)
__device__ __forceinline__ void flush_stage_f(const float* __restrict__ st,
                                              float* __restrict__ C,
                                              int bm, int bn, int ldc,
                                              int wid, int lane)
{
#pragma unroll
    for (int i = 0; i < 16; i++) {
        const int row = i * 8 + wid;
        float4 v = *(const float4*)&st[row * FPITCH + lane * 4];
        *(float4*)&C[(long)(bm + row) * ldc + bn + lane * 4] = v;
    }
}

// Shared mainloop + epilogue. A,B,C pre-offset to batch base; bm/bn are tile
// origins inside the batch. mb = mask row base (EPI 1), rs = rowsum base (1,2).
// For EPI 1, alpha is pre-multiplied by log2(e).
template <typename OutT, int EPI>
__device__ __forceinline__ void gemm_core(
    const __half* __restrict__ A, const __half* __restrict__ Bm,
    OutT* __restrict__ C, int K, int lda, int ldb, int ldc,
    int bm, int bn, float alpha,
    const int* __restrict__ mb, float* __restrict__ rs)
{
    extern __shared__ __half smem[];
    const uint32_t sb = smem_u32(smem);
    const int tid = threadIdx.x;
    const int wid = tid >> 5, lane = tid & 31;
    const int g8 = lane >> 3, rr = lane & 7;
    const int wm = (wid & 3) * 32, wn = (wid >> 2) * 64;
    const int acs = g8 >> 1;
    const int bcs = g8 & 1;

    uint32_t rowA[2], rowB[4];
#pragma unroll
    for (int t = 0; t < 2; t++)
        rowA[t] = (uint32_t)(wm + t * 16 + (g8 & 1) * 8 + rr) * 128u;
#pragma unroll
    for (int t = 0; t < 4; t++)
        rowB[t] = (uint32_t)(wn + t * 16 + (g8 >> 1) * 8 + rr) * 128u + 16384u;

    const __half* Ag = A + (long)bm * lda;
    const __half* Bg = Bm + (long)bn * ldb;

    float acc[2][8][4];
#pragma unroll
    for (int mt = 0; mt < 2; mt++)
#pragma unroll
        for (int nt = 0; nt < 8; nt++)
#pragma unroll
            for (int q = 0; q < 4; q++) acc[mt][nt][q] = 0.f;

    const int KC = K >> 6;

    stage_cp(sb,                 Ag, lda, 0, tid);
    stage_cp(sb + 16384u,        Bg, ldb, 0, tid);
    asm volatile("cp.async.commit_group;" ::: "memory");
    stage_cp(sb + BUFS,          Ag, lda, 64, tid);
    stage_cp(sb + BUFS + 16384u, Bg, ldb, 64, tid);
    asm volatile("cp.async.commit_group;" ::: "memory");

    int bufc = 0;
    for (int c = 0; c < KC; c++) {
        if (c + 1 < KC)
            asm volatile("cp.async.wait_group 1;" ::: "memory");
        else
            asm volatile("cp.async.wait_group 0;" ::: "memory");
        __syncthreads();

        if (c + 2 < KC) {
            int si = bufc + 2; if (si >= 3) si -= 3;
            const uint32_t ss = sb + (uint32_t)si * BUFS;
            stage_cp(ss,          Ag, lda, (c + 2) * 64, tid);
            stage_cp(ss + 16384u, Bg, ldb, (c + 2) * 64, tid);
        }
        asm volatile("cp.async.commit_group;" ::: "memory");

        const uint32_t ab = sb + (uint32_t)bufc * BUFS;
#pragma unroll
        for (int ks = 0; ks < 4; ks++) {
            const uint32_t sca = (uint32_t)(((2 * ks + acs) ^ rr) * 16);
            const uint32_t scb = (uint32_t)(((2 * ks + bcs) ^ rr) * 16);
            uint32_t a[2][4], b[4][4];
#pragma unroll
            for (int mt = 0; mt < 2; mt++) ldm_x4(a[mt], ab + rowA[mt] + sca);
#pragma unroll
            for (int np = 0; np < 4; np++) ldm_x4(b[np], ab + rowB[np] + scb);
#pragma unroll
            for (int mt = 0; mt < 2; mt++)
#pragma unroll
                for (int np = 0; np < 4; np++) {
                    mma16(acc[mt][2 * np],     a[mt], b[np][0], b[np][1]);
                    mma16(acc[mt][2 * np + 1], a[mt], b[np][2], b[np][3]);
                }
        }
        bufc++; if (bufc == 3) bufc = 0;
    }

    // ---------------- epilogue ----------------
    const int g = lane >> 2, t4 = lane & 3;
    __syncthreads();                       // all warps done reading smem tiles

    if (EPI == 0 && sizeof(OutT) == 4) {
        // float output (out-proj): smem-staged coalesced stores
        float* stf = (float*)smem;
#pragma unroll
        for (int mt = 0; mt < 2; mt++) {
            const int r0 = wm + mt * 16 + g;
#pragma unroll
            for (int nt = 0; nt < 8; nt++) {
                const int c0 = wn + nt * 8 + t4 * 2;
                *(float2*)&stf[r0 * FPITCH + c0] =
                    make_float2(alpha * acc[mt][nt][0], alpha * acc[mt][nt][1]);
                *(float2*)&stf[(r0 + 8) * FPITCH + c0] =
                    make_float2(alpha * acc[mt][nt][2], alpha * acc[mt][nt][3]);
            }
        }
        __syncthreads();
        flush_stage_f(stf, (float*)C, bm, bn, ldc, wid, lane);
        return;
    }

    // half outputs: smem-transposed path
    uint32_t* st = (uint32_t*)smem;

    if (EPI == 1) {
        const float shift2 = EXP_SHIFT * LOG2E;
        int2 mc[8];
#pragma unroll
        for (int nt = 0; nt < 8; nt++) {
            const int c0 = bn + wn + nt * 8 + t4 * 2;
            mc[nt] = *(const int2*)&mb[c0];
        }
#pragma unroll
        for (int mt = 0; mt < 2; mt++) {
            const int r0 = wm + mt * 16 + g;   // local row
            const int gr0 = bm + r0;
            const int mr0 = mb[gr0], mr1 = mb[gr0 + 8];
            float s0 = 0.f, s1 = 0.f;
#pragma unroll
            for (int nt = 0; nt < 8; nt++) {
                const int j = (wn >> 1) + nt * 4 + t4;
                float e00 = (mr0 && mc[nt].x) ? ex2(fmaf(acc[mt][nt][0], alpha, -shift2)) : 0.f;
                float e01 = (mr0 && mc[nt].y) ? ex2(fmaf(acc[mt][nt][1], alpha, -shift2)) : 0.f;
                float e10 = (mr1 && mc[nt].x) ? ex2(fmaf(acc[mt][nt][2], alpha, -shift2)) : 0.f;
                float e11 = (mr1 && mc[nt].y) ? ex2(fmaf(acc[mt][nt][3], alpha, -shift2)) : 0.f;
                s0 += e00 + e01;
                s1 += e10 + e11;
                st[r0 * EPITCH + j]       = pack2(e00, e01);
                st[(r0 + 8) * EPITCH + j] = pack2(e10, e11);
            }
            s0 += __shfl_xor_sync(0xffffffffu, s0, 1);
            s0 += __shfl_xor_sync(0xffffffffu, s0, 2);
            s1 += __shfl_xor_sync(0xffffffffu, s1, 1);
            s1 += __shfl_xor_sync(0xffffffffu, s1, 2);
            if (t4 == 0) {
                atomicAdd(&rs[gr0], s0);
                atomicAdd(&rs[gr0 + 8], s1);
            }
        }
    } else if (EPI == 2) {
        float d0[2], d1[2];
#pragma unroll
        for (int mt = 0; mt < 2; mt++) {
            const int gr0 = bm + wm + mt * 16 + g;
            d0[mt] = rs[gr0];
            d1[mt] = rs[gr0 + 8];
        }
#pragma unroll
        for (int mt = 0; mt < 2; mt++) {
            const int r0 = wm + mt * 16 + g;
            const float inv0 = (d0[mt] > 0.f) ? 1.f / d0[mt] : 0.f;
            const float inv1 = (d1[mt] > 0.f) ? 1.f / d1[mt] : 0.f;
#pragma unroll
            for (int nt = 0; nt < 8; nt++) {
                const int j = (wn >> 1) + nt * 4 + t4;
                st[r0 * EPITCH + j]       = pack2(inv0 * acc[mt][nt][0], inv0 * acc[mt][nt][1]);
                st[(r0 + 8) * EPITCH + j] = pack2(inv1 * acc[mt][nt][2], inv1 * acc[mt][nt][3]);
            }
        }
    } else {
        // EPI 0, half output
#pragma unroll
        for (int mt = 0; mt < 2; mt++) {
            const int r0 = wm + mt * 16 + g;
#pragma unroll
            for (int nt = 0; nt < 8; nt++) {
                const int j = (wn >> 1) + nt * 4 + t4;
                st[r0 * EPITCH + j]       = pack2(alpha * acc[mt][nt][0], alpha * acc[mt][nt][1]);
                st[(r0 + 8) * EPITCH + j] = pack2(alpha * acc[mt][nt][2], alpha * acc[mt][nt][3]);
            }
        }
    }

    __syncthreads();
    flush_stage_h(st, (__half*)C, bm, bn, ldc, wid, lane);
}

// generic batched GEMM wrapper (logits / PV / out-proj)
template <typename OutT, int EPI>
__global__ void __launch_bounds__(256, 2)
gemm_h(const __half* __restrict__ A, const __half* __restrict__ Bm,
       OutT* __restrict__ C,
       int K, int lda, int ldb, int ldc, int Z2,
       long sA1, long sA2, long sB1, long sB2, long sC1, long sC2,
       float alpha, const int* __restrict__ mask, float* __restrict__ rowsum)
{
    const int z = blockIdx.z, z1 = z / Z2, z2 = z % Z2;
    A  += z1 * sA1 + z2 * sA2;
    Bm += z1 * sB1 + z2 * sB2;
    C  += z1 * sC1 + z2 * sC2;
    const int bm = blockIdx.y * 128;
    const int bn = blockIdx.x * 128;
    const int* mb = (EPI == 1) ? (mask + (long)z1 * Sdim) : nullptr;
    float* rs = (EPI >= 1) ? (rowsum + ((long)z1 * Hdim + z2) * (long)Sdim) : nullptr;
    gemm_core<OutT, EPI>(A, Bm, C, K, lda, ldb, ldc, bm, bn, alpha, mb, rs);
}

// fused Q-proj / K-proj / V^T-proj: one launch, 6144 CTAs.
// grid (64, 1, 96): z = op*32 + h*4 + b ; flat tile decode per op.
__global__ void __launch_bounds__(256, 2)
qkv_kernel(const __half* __restrict__ hx,
           const __half* __restrict__ hwq, const __half* __restrict__ hwk,
           const __half* __restrict__ hwv,
           __half* __restrict__ hq, __half* __restrict__ hk,
           __half* __restrict__ hv)
{
    const long SD = (long)Sdim * Ddim;
    const long DD = (long)Ddim * Ddim;
    const int z = blockIdx.z;
    const int op = z >> 5;                 // 0=Q, 1=K, 2=V^T
    const int zz = z & 31;
    const int h = zz >> 2, b = zz & 3;
    const int flat = blockIdx.x;           // 0..63

    if (op < 2) {
        const int bm = (flat >> 2) * 128;
        const int bn = (flat & 3) * 128;
        const __half* A = hx + (long)b * SD;
        const __half* B = (op ? hwk : hwq) + (long)h * DD;
        __half* C = (op ? hk : hq) + (long)b * Hdim * SD + (long)h * SD;
        gemm_core<__half, 0>(A, B, C, Ddim, Ddim, Ddim, Ddim, bm, bn,
                             1.f, nullptr, nullptr);
    } else {
        const int bm = (flat >> 4) * 128;
        const int bn = (flat & 15) * 128;
        const __half* A = hwv + (long)h * DD;
        const __half* B = hx + (long)b * SD;
        __half* C = hv + (long)b * Hdim * SD + (long)h * SD;
        gemm_core<__half, 0>(A, B, C, Ddim, Ddim, Ddim, Sdim, bm, bn,
                             1.f, nullptr, nullptr);
    }
}

// ---------------- fused prep: all fp32->fp16 converts + rowsum zero ----------------
// 4 float4 per thread (MLP=4), grid-stride regions decoded per index.
#define NX4   1048576
#define NW4   524288
#define NRS4  16384
#define NTOT4 (NX4 + 4 * NW4 + NRS4)       // 3162112
#define PREP_THREADS (NTOT4 / 4)           // 790528 = 3088 * 256

struct PrepArgs {
    const float *x, *wq, *wk, *wv, *wp;
    __half *hx, *hwq, *hwk, *hwv, *hwp;
    float* rs;
};

__device__ __forceinline__ void prep_one(const PrepArgs& a, long i) {
    const float* in;
    __half* out;
    if (i < NX4) { in = a.x; out = a.hx; }
    else {
        i -= NX4;
        if (i < NW4) { in = a.wq; out = a.hwq; }
        else {
            i -= NW4;
            if (i < NW4) { in = a.wk; out = a.hwk; }
            else {
                i -= NW4;
                if (i < NW4) { in = a.wv; out = a.hwv; }
                else {
                    i -= NW4;
                    if (i < NW4) { in = a.wp; out = a.hwp; }
                    else {
                        i -= NW4;
                        ((float4*)a.rs)[i] = make_float4(0.f, 0.f, 0.f, 0.f);
                        return;
                    }
                }
            }
        }
    }
    float4 v = ((const float4*)in)[i];
    __half2 h0 = __floats2half2_rn(v.x, v.y);
    __half2 h1 = __floats2half2_rn(v.z, v.w);
    uint2 u;
    u.x = *(uint32_t*)&h0;
    u.y = *(uint32_t*)&h1;
    ((uint2*)out)[i] = u;
}

__global__ void prep_kernel(PrepArgs a)
{
    const long i0 = (long)blockIdx.x * 256 + threadIdx.x;
#pragma unroll
    for (int k = 0; k < 4; k++)
        prep_one(a, i0 + (long)k * PREP_THREADS);
}

// ---------------- launcher ----------------
extern "C" void kernel_launch(void* const* d_in, const int* in_sizes, int n_in,
                              void* d_out, int out_size)
{
    (void)in_sizes; (void)n_in; (void)out_size;
    const float* x    = (const float*)d_in[0];
    const int*   mask = (const int*)d_in[1];
    const float* Wq   = (const float*)d_in[2];
    const float* Wk   = (const float*)d_in[3];
    const float* Wv   = (const float*)d_in[4];
    const float* Wp   = (const float*)d_in[5];
    float* out = (float*)d_out;

    __half *hx, *hwq, *hwk, *hwv, *hwp, *hq, *hk, *hv, *hp, *hc;
    float* rs;
    cudaGetSymbolAddress((void**)&hx,  g_x);
    cudaGetSymbolAddress((void**)&hwq, g_wq);
    cudaGetSymbolAddress((void**)&hwk, g_wk);
    cudaGetSymbolAddress((void**)&hwv, g_wv);
    cudaGetSymbolAddress((void**)&hwp, g_wp);
    cudaGetSymbolAddress((void**)&hq,  g_q);
    cudaGetSymbolAddress((void**)&hk,  g_k);
    cudaGetSymbolAddress((void**)&hv,  g_v);
    cudaGetSymbolAddress((void**)&hp,  g_p);
    cudaGetSymbolAddress((void**)&hc,  g_c);
    cudaGetSymbolAddress((void**)&rs,  g_rs);

    cudaFuncSetAttribute((const void*)qkv_kernel, cudaFuncAttributeMaxDynamicSharedMemorySize, SM_TOTAL);
    cudaFuncSetAttribute((const void*)gemm_h<__half, 1>, cudaFuncAttributeMaxDynamicSharedMemorySize, SM_TOTAL);
    cudaFuncSetAttribute((const void*)gemm_h<__half, 2>, cudaFuncAttributeMaxDynamicSharedMemorySize, SM_TOTAL);
    cudaFuncSetAttribute((const void*)gemm_h<float, 0>,  cudaFuncAttributeMaxDynamicSharedMemorySize, SM_TOTAL);

    const long SD = (long)Sdim * Ddim;      // 1048576
    const long SS = (long)Sdim * Sdim;      // 4194304
    const float scale = 1.0f / sqrtf((float)Ddim);
    dim3 blk(256);

    // 0) fused convert + rowsum zero (one launch, MLP=4)
    {
        PrepArgs a;
        a.x = x; a.wq = Wq; a.wk = Wk; a.wv = Wv; a.wp = Wp;
        a.hx = hx; a.hwq = hwq; a.hwk = hwk; a.hwv = hwv; a.hwp = hwp;
        a.rs = rs;
        prep_kernel<<<PREP_THREADS / 256, 256>>>(a);
    }

    // 1) fused Q-proj + K-proj + V^T-proj (one launch, 6144 CTAs)
    {
        dim3 grid(64, 1, 96);
        qkv_kernel<<<grid, blk, SM_TOTAL>>>(hx, hwq, hwk, hwv, hq, hk, hv);
    }

    // 2) logits + masked exp2 + rowsum (M=N=S,K=D); z1=b (Z2=H), z2=h
    {
        dim3 grid(Sdim / 128, Sdim / 128, Bdim * Hdim);
        gemm_h<__half, 1><<<grid, blk, SM_TOTAL>>>(hq, hk, hp, Ddim, Ddim, Ddim, Sdim,
                                                   Hdim, Hdim * SD, SD, Hdim * SD, SD,
                                                   Hdim * SS, SS,
                                                   scale * LOG2E, mask, rs);
    }

    // 3) PV with rowsum normalization (M=S,N=D,K=S) -> concat; z1=b, z2=h
    {
        dim3 grid(Ddim / 128, Sdim / 128, Bdim * Hdim);
        gemm_h<__half, 2><<<grid, blk, SM_TOTAL>>>(hp, hv, hc, Sdim, Sdim, Sdim,
                                                   Hdim * Ddim, Hdim,
                                                   (long)Hdim * SS, SS,
                                                   (long)Hdim * SD, SD,
                                                   (long)Sdim * Hdim * Ddim, (long)Ddim,
                                                   1.f, nullptr, rs);
    }

    // 4) out proj (M=S,N=D,K=H*D), z=b
    {
        dim3 grid(Ddim / 128, Sdim / 128, Bdim);
        gemm_h<float, 0><<<grid, blk, SM_TOTAL>>>(hc, hwp, out, Hdim * Ddim,
                                                  Hdim * Ddim, Hdim * Ddim, Ddim, 1,
                                                  (long)Sdim * Hdim * Ddim, 0, 0, 0,
                                                  SD, 0, 1.f, nullptr, nullptr);
    }
}

// round 17
// speedup vs baseline: 1.0146x; 1.0146x over previous
#include <cuda_runtime.h>
#include <cuda_fp16.h>
#include <cstdint>
#include <math.h>

#define Bdim 4
#define Sdim 2048
#define Ddim 512
#define Hdim 8

// half scratch (device globals: allocation-free)
__device__ __half g_x [(size_t)Bdim * Sdim * Ddim];
__device__ __half g_wq[(size_t)Hdim * Ddim * Ddim];
__device__ __half g_wk[(size_t)Hdim * Ddim * Ddim];
__device__ __half g_wv[(size_t)Hdim * Ddim * Ddim];
__device__ __half g_wp[(size_t)Ddim * Hdim * Ddim];
__device__ __half g_q [(size_t)Bdim * Hdim * Sdim * Ddim];   // [b][h][s][e]
__device__ __half g_k [(size_t)Bdim * Hdim * Sdim * Ddim];   // [b][h][t][e]
__device__ __half g_v [(size_t)Bdim * Hdim * Sdim * Ddim];   // V^T: [b][h][e][t]
__device__ __half g_p [(size_t)Bdim * Hdim * Sdim * Sdim];   // exp(logit-4), unnormalized
__device__ __half g_c [(size_t)Bdim * Sdim * Hdim * Ddim];   // concat
__device__ float  g_rs[(size_t)Bdim * Hdim * Sdim];          // row sums

#define EXP_SHIFT 4.0f
#define LOG2E 1.4426950408889634f

// ---------------- fp16 mma.sync GEMM core (all-NT, fp32 accum) ----------------
// CTA 128x128, 256 threads (8 warps, 4x2), warp tile 32x64.
// K-chunk 64 halves, 3-stage cp.async pipeline, XOR-16B swizzle,
// ldmatrix.x4, m16n8k16 fp32-acc. 16 warps/SM at 2 CTAs/SM (RF-limited).
// Half outputs: smem-transposed coalesced epilogue (uint4 rows).
// Float outputs (out-proj): direct STG.64 (2-sector, cheap enough).
// EPI: 0 = plain, 1 = masked exp2 + row-sum atomics, 2 = rowsum normalize.

#define BUFS   32768                       // A tile 16KB + B tile 16KB
#define SM_TOTAL (3 * BUFS)                // 98304 bytes
#define EPITCH 68                          // half-stage pitch in uints (272B/row)

__device__ __forceinline__ uint32_t smem_u32(const void* p) {
    uint32_t a;
    asm("{ .reg .u64 t; cvta.to.shared.u64 t, %1; cvt.u32.u64 %0, t; }"
        : "=r"(a) : "l"(p));
    return a;
}

__device__ __forceinline__ void cpasync16(uint32_t dst, const void* src) {
    asm volatile("cp.async.cg.shared.global [%0], [%1], 16;"
                 :: "r"(dst), "l"(src) : "memory");
}

__device__ __forceinline__ void mma16(float* c, const uint32_t* a,
                                      uint32_t b0, uint32_t b1) {
    asm volatile(
        "mma.sync.aligned.m16n8k16.row.col.f32.f16.f16.f32 "
        "{%0,%1,%2,%3}, {%4,%5,%6,%7}, {%8,%9}, {%0,%1,%2,%3};\n"
        : "+f"(c[0]), "+f"(c[1]), "+f"(c[2]), "+f"(c[3])
        : "r"(a[0]), "r"(a[1]), "r"(a[2]), "r"(a[3]), "r"(b0), "r"(b1));
}

__device__ __forceinline__ void ldm_x4(uint32_t* r, uint32_t addr) {
    asm volatile(
        "ldmatrix.sync.aligned.m8n8.x4.shared.b16 {%0,%1,%2,%3}, [%4];"
        : "=r"(r[0]), "=r"(r[1]), "=r"(r[2]), "=r"(r[3]) : "r"(addr));
}

__device__ __forceinline__ float ex2(float x) {
    float r;
    asm("ex2.approx.f32 %0, %1;" : "=f"(r) : "f"(x));
    return r;
}

__device__ __forceinline__ uint32_t pack2(float v0, float v1) {
    __half2 h = __floats2half2_rn(v0, v1);
    return *(uint32_t*)&h;
}

// stage one 128row x 64half tile via 4 cp.async.16B per thread (256 thr)
__device__ __forceinline__ void stage_cp(uint32_t sbuf, const __half* __restrict__ g,
                                         long ld, int kofs, int tid) {
#pragma unroll
    for (int i = 0; i < 4; i++) {
        const int idx = tid + i * 256;
        const int m = idx >> 3, ch = idx & 7;
        const int sc = ch ^ (m & 7);
        cpasync16(sbuf + (uint32_t)(m * 128 + sc * 16),
                  g + (long)m * ld + kofs + ch * 8);
    }
}

__device__ __forceinline__ void store2f(float* C, long off, float v0, float v1) {
    *(float2*)&C[off] = make_float2(v0, v1);
}

// cooperative coalesced flush of the 128x128-half stage -> global
__device__ __forceinline__ void flush_stage_h(const uint32_t* __restrict__ st,
                                              __half* __restrict__ C,
                                              int bm, int bn, int ldc,
                                              int wid, int lane)
{
#pragma unroll
    for (int i = 0; i < 8; i++) {
        const int row = i * 16 + wid * 2 + (lane >> 4);
        const int l16 = lane & 15;
        uint4 v = *(const uint4*)&st[row * EPITCH + l16 * 4];
        *(uint4*)&C[(long)(bm + row) * ldc + bn + l16 * 8] = v;
    }
}

// Shared mainloop + epilogue. A,B,C pre-offset to batch base; bm/bn are tile
// origins inside the batch. mb = mask row base (EPI 1), rs = rowsum base (1,2).
// For EPI 1, alpha is pre-multiplied by log2(e).
template <typename OutT, int EPI>
__device__ __forceinline__ void gemm_core(
    const __half* __restrict__ A, const __half* __restrict__ Bm,
    OutT* __restrict__ C, int K, int lda, int ldb, int ldc,
    int bm, int bn, float alpha,
    const int* __restrict__ mb, float* __restrict__ rs)
{
    extern __shared__ __half smem[];
    const uint32_t sb = smem_u32(smem);
    const int tid = threadIdx.x;
    const int wid = tid >> 5, lane = tid & 31;
    const int g8 = lane >> 3, rr = lane & 7;
    const int wm = (wid & 3) * 32, wn = (wid >> 2) * 64;
    const int acs = g8 >> 1;
    const int bcs = g8 & 1;

    uint32_t rowA[2], rowB[4];
#pragma unroll
    for (int t = 0; t < 2; t++)
        rowA[t] = (uint32_t)(wm + t * 16 + (g8 & 1) * 8 + rr) * 128u;
#pragma unroll
    for (int t = 0; t < 4; t++)
        rowB[t] = (uint32_t)(wn + t * 16 + (g8 >> 1) * 8 + rr) * 128u + 16384u;

    const __half* Ag = A + (long)bm * lda;
    const __half* Bg = Bm + (long)bn * ldb;

    float acc[2][8][4];
#pragma unroll
    for (int mt = 0; mt < 2; mt++)
#pragma unroll
        for (int nt = 0; nt < 8; nt++)
#pragma unroll
            for (int q = 0; q < 4; q++) acc[mt][nt][q] = 0.f;

    const int KC = K >> 6;

    stage_cp(sb,                 Ag, lda, 0, tid);
    stage_cp(sb + 16384u,        Bg, ldb, 0, tid);
    asm volatile("cp.async.commit_group;" ::: "memory");
    stage_cp(sb + BUFS,          Ag, lda, 64, tid);
    stage_cp(sb + BUFS + 16384u, Bg, ldb, 64, tid);
    asm volatile("cp.async.commit_group;" ::: "memory");

    int bufc = 0;
    for (int c = 0; c < KC; c++) {
        if (c + 1 < KC)
            asm volatile("cp.async.wait_group 1;" ::: "memory");
        else
            asm volatile("cp.async.wait_group 0;" ::: "memory");
        __syncthreads();

        if (c + 2 < KC) {
            int si = bufc + 2; if (si >= 3) si -= 3;
            const uint32_t ss = sb + (uint32_t)si * BUFS;
            stage_cp(ss,          Ag, lda, (c + 2) * 64, tid);
            stage_cp(ss + 16384u, Bg, ldb, (c + 2) * 64, tid);
        }
        asm volatile("cp.async.commit_group;" ::: "memory");

        const uint32_t ab = sb + (uint32_t)bufc * BUFS;
#pragma unroll
        for (int ks = 0; ks < 4; ks++) {
            const uint32_t sca = (uint32_t)(((2 * ks + acs) ^ rr) * 16);
            const uint32_t scb = (uint32_t)(((2 * ks + bcs) ^ rr) * 16);
            uint32_t a[2][4], b[4][4];
#pragma unroll
            for (int mt = 0; mt < 2; mt++) ldm_x4(a[mt], ab + rowA[mt] + sca);
#pragma unroll
            for (int np = 0; np < 4; np++) ldm_x4(b[np], ab + rowB[np] + scb);
#pragma unroll
            for (int mt = 0; mt < 2; mt++)
#pragma unroll
                for (int np = 0; np < 4; np++) {
                    mma16(acc[mt][2 * np],     a[mt], b[np][0], b[np][1]);
                    mma16(acc[mt][2 * np + 1], a[mt], b[np][2], b[np][3]);
                }
        }
        bufc++; if (bufc == 3) bufc = 0;
    }

    // ---------------- epilogue ----------------
    const int g = lane >> 2, t4 = lane & 3;

    if (EPI == 0 && sizeof(OutT) == 4) {
        // float output (out-proj): direct stores (2-sector STG.64, cheap)
        float* Cf = (float*)C;
#pragma unroll
        for (int mt = 0; mt < 2; mt++) {
#pragma unroll
            for (int nt = 0; nt < 8; nt++) {
                const int r0 = bm + wm + mt * 16 + g;
                const int c0 = bn + wn + nt * 8 + t4 * 2;
                store2f(Cf, (long)r0 * ldc + c0,
                        alpha * acc[mt][nt][0], alpha * acc[mt][nt][1]);
                store2f(Cf, (long)(r0 + 8) * ldc + c0,
                        alpha * acc[mt][nt][2], alpha * acc[mt][nt][3]);
            }
        }
        return;
    }

    // half outputs: smem-transposed path. Stage at smem base (mainloop done).
    uint32_t* st = (uint32_t*)smem;
    __syncthreads();                       // all warps done reading smem tiles

    if (EPI == 1) {
        const float shift2 = EXP_SHIFT * LOG2E;
        int2 mc[8];
#pragma unroll
        for (int nt = 0; nt < 8; nt++) {
            const int c0 = bn + wn + nt * 8 + t4 * 2;
            mc[nt] = *(const int2*)&mb[c0];
        }
#pragma unroll
        for (int mt = 0; mt < 2; mt++) {
            const int r0 = wm + mt * 16 + g;   // local row
            const int gr0 = bm + r0;
            const int mr0 = mb[gr0], mr1 = mb[gr0 + 8];
            float s0 = 0.f, s1 = 0.f;
#pragma unroll
            for (int nt = 0; nt < 8; nt++) {
                const int j = (wn >> 1) + nt * 4 + t4;
                float e00 = (mr0 && mc[nt].x) ? ex2(fmaf(acc[mt][nt][0], alpha, -shift2)) : 0.f;
                float e01 = (mr0 && mc[nt].y) ? ex2(fmaf(acc[mt][nt][1], alpha, -shift2)) : 0.f;
                float e10 = (mr1 && mc[nt].x) ? ex2(fmaf(acc[mt][nt][2], alpha, -shift2)) : 0.f;
                float e11 = (mr1 && mc[nt].y) ? ex2(fmaf(acc[mt][nt][3], alpha, -shift2)) : 0.f;
                s0 += e00 + e01;
                s1 += e10 + e11;
                st[r0 * EPITCH + j]       = pack2(e00, e01);
                st[(r0 + 8) * EPITCH + j] = pack2(e10, e11);
            }
            s0 += __shfl_xor_sync(0xffffffffu, s0, 1);
            s0 += __shfl_xor_sync(0xffffffffu, s0, 2);
            s1 += __shfl_xor_sync(0xffffffffu, s1, 1);
            s1 += __shfl_xor_sync(0xffffffffu, s1, 2);
            if (t4 == 0) {
                atomicAdd(&rs[gr0], s0);
                atomicAdd(&rs[gr0 + 8], s1);
            }
        }
    } else if (EPI == 2) {
        float d0[2], d1[2];
#pragma unroll
        for (int mt = 0; mt < 2; mt++) {
            const int gr0 = bm + wm + mt * 16 + g;
            d0[mt] = rs[gr0];
            d1[mt] = rs[gr0 + 8];
        }
#pragma unroll
        for (int mt = 0; mt < 2; mt++) {
            const int r0 = wm + mt * 16 + g;
            const float inv0 = (d0[mt] > 0.f) ? 1.f / d0[mt] : 0.f;
            const float inv1 = (d1[mt] > 0.f) ? 1.f / d1[mt] : 0.f;
#pragma unroll
            for (int nt = 0; nt < 8; nt++) {
                const int j = (wn >> 1) + nt * 4 + t4;
                st[r0 * EPITCH + j]       = pack2(inv0 * acc[mt][nt][0], inv0 * acc[mt][nt][1]);
                st[(r0 + 8) * EPITCH + j] = pack2(inv1 * acc[mt][nt][2], inv1 * acc[mt][nt][3]);
            }
        }
    } else {
        // EPI 0, half output
#pragma unroll
        for (int mt = 0; mt < 2; mt++) {
            const int r0 = wm + mt * 16 + g;
#pragma unroll
            for (int nt = 0; nt < 8; nt++) {
                const int j = (wn >> 1) + nt * 4 + t4;
                st[r0 * EPITCH + j]       = pack2(alpha * acc[mt][nt][0], alpha * acc[mt][nt][1]);
                st[(r0 + 8) * EPITCH + j] = pack2(alpha * acc[mt][nt][2], alpha * acc[mt][nt][3]);
            }
        }
    }

    __syncthreads();
    flush_stage_h(st, (__half*)C, bm, bn, ldc, wid, lane);
}

// generic batched GEMM wrapper (logits / PV / out-proj) with 4x4 tile raster
template <typename OutT, int EPI>
__global__ void __launch_bounds__(256, 2)
gemm_h(const __half* __restrict__ A, const __half* __restrict__ Bm,
       OutT* __restrict__ C,
       int K, int lda, int ldb, int ldc, int Z2,
       long sA1, long sA2, long sB1, long sB2, long sC1, long sC2,
       float alpha, const int* __restrict__ mask, float* __restrict__ rowsum)
{
    const int z = blockIdx.z, z1 = z / Z2, z2 = z % Z2;
    A  += z1 * sA1 + z2 * sA2;
    Bm += z1 * sB1 + z2 * sB2;
    C  += z1 * sC1 + z2 * sC2;

    // 4x4 super-tile rasterization for better joint A+B L2 reuse.
    // gridDim.x is always a multiple of 4 here (4 or 16).
    const int flat = blockIdx.y * gridDim.x + blockIdx.x;
    const int supw = gridDim.x >> 2;       // super-tiles per row
    const int sup = flat >> 4, loc = flat & 15;
    const int bx = (sup % supw) * 4 + (loc & 3);
    const int by = (sup / supw) * 4 + (loc >> 2);
    const int bm = by * 128;
    const int bn = bx * 128;

    const int* mb = (EPI == 1) ? (mask + (long)z1 * Sdim) : nullptr;
    float* rs = (EPI >= 1) ? (rowsum + ((long)z1 * Hdim + z2) * (long)Sdim) : nullptr;
    gemm_core<OutT, EPI>(A, Bm, C, K, lda, ldb, ldc, bm, bn, alpha, mb, rs);
}

// fused Q-proj / K-proj / V^T-proj: one launch, 6144 CTAs.
// grid (64, 1, 96): z = op*32 + h*4 + b ; flat tile decode per op.
__global__ void __launch_bounds__(256, 2)
qkv_kernel(const __half* __restrict__ hx,
           const __half* __restrict__ hwq, const __half* __restrict__ hwk,
           const __half* __restrict__ hwv,
           __half* __restrict__ hq, __half* __restrict__ hk,
           __half* __restrict__ hv)
{
    const long SD = (long)Sdim * Ddim;
    const long DD = (long)Ddim * Ddim;
    const int z = blockIdx.z;
    const int op = z >> 5;                 // 0=Q, 1=K, 2=V^T
    const int zz = z & 31;
    const int h = zz >> 2, b = zz & 3;
    const int flat = blockIdx.x;           // 0..63

    if (op < 2) {
        const int bm = (flat >> 2) * 128;
        const int bn = (flat & 3) * 128;
        const __half* A = hx + (long)b * SD;
        const __half* B = (op ? hwk : hwq) + (long)h * DD;
        __half* C = (op ? hk : hq) + (long)b * Hdim * SD + (long)h * SD;
        gemm_core<__half, 0>(A, B, C, Ddim, Ddim, Ddim, Ddim, bm, bn,
                             1.f, nullptr, nullptr);
    } else {
        const int bm = (flat >> 4) * 128;
        const int bn = (flat & 15) * 128;
        const __half* A = hwv + (long)h * DD;
        const __half* B = hx + (long)b * SD;
        __half* C = hv + (long)b * Hdim * SD + (long)h * SD;
        gemm_core<__half, 0>(A, B, C, Ddim, Ddim, Ddim, Sdim, bm, bn,
                             1.f, nullptr, nullptr);
    }
}

// ---------------- fused prep: all fp32->fp16 converts + rowsum zero ----------------
// 4 float4 per thread (MLP=4), grid-stride regions decoded per index.
#define NX4   1048576
#define NW4   524288
#define NRS4  16384
#define NTOT4 (NX4 + 4 * NW4 + NRS4)       // 3162112
#define PREP_THREADS (NTOT4 / 4)           // 790528 = 3088 * 256

struct PrepArgs {
    const float *x, *wq, *wk, *wv, *wp;
    __half *hx, *hwq, *hwk, *hwv, *hwp;
    float* rs;
};

__device__ __forceinline__ void prep_one(const PrepArgs& a, long i) {
    const float* in;
    __half* out;
    if (i < NX4) { in = a.x; out = a.hx; }
    else {
        i -= NX4;
        if (i < NW4) { in = a.wq; out = a.hwq; }
        else {
            i -= NW4;
            if (i < NW4) { in = a.wk; out = a.hwk; }
            else {
                i -= NW4;
                if (i < NW4) { in = a.wv; out = a.hwv; }
                else {
                    i -= NW4;
                    if (i < NW4) { in = a.wp; out = a.hwp; }
                    else {
                        i -= NW4;
                        ((float4*)a.rs)[i] = make_float4(0.f, 0.f, 0.f, 0.f);
                        return;
                    }
                }
            }
        }
    }
    float4 v = ((const float4*)in)[i];
    __half2 h0 = __floats2half2_rn(v.x, v.y);
    __half2 h1 = __floats2half2_rn(v.z, v.w);
    uint2 u;
    u.x = *(uint32_t*)&h0;
    u.y = *(uint32_t*)&h1;
    ((uint2*)out)[i] = u;
}

__global__ void prep_kernel(PrepArgs a)
{
    const long i0 = (long)blockIdx.x * 256 + threadIdx.x;
#pragma unroll
    for (int k = 0; k < 4; k++)
        prep_one(a, i0 + (long)k * PREP_THREADS);
}

// ---------------- launcher ----------------
extern "C" void kernel_launch(void* const* d_in, const int* in_sizes, int n_in,
                              void* d_out, int out_size)
{
    (void)in_sizes; (void)n_in; (void)out_size;
    const float* x    = (const float*)d_in[0];
    const int*   mask = (const int*)d_in[1];
    const float* Wq   = (const float*)d_in[2];
    const float* Wk   = (const float*)d_in[3];
    const float* Wv   = (const float*)d_in[4];
    const float* Wp   = (const float*)d_in[5];
    float* out = (float*)d_out;

    __half *hx, *hwq, *hwk, *hwv, *hwp, *hq, *hk, *hv, *hp, *hc;
    float* rs;
    cudaGetSymbolAddress((void**)&hx,  g_x);
    cudaGetSymbolAddress((void**)&hwq, g_wq);
    cudaGetSymbolAddress((void**)&hwk, g_wk);
    cudaGetSymbolAddress((void**)&hwv, g_wv);
    cudaGetSymbolAddress((void**)&hwp, g_wp);
    cudaGetSymbolAddress((void**)&hq,  g_q);
    cudaGetSymbolAddress((void**)&hk,  g_k);
    cudaGetSymbolAddress((void**)&hv,  g_v);
    cudaGetSymbolAddress((void**)&hp,  g_p);
    cudaGetSymbolAddress((void**)&hc,  g_c);
    cudaGetSymbolAddress((void**)&rs,  g_rs);

    cudaFuncSetAttribute((const void*)qkv_kernel, cudaFuncAttributeMaxDynamicSharedMemorySize, SM_TOTAL);
    cudaFuncSetAttribute((const void*)gemm_h<__half, 1>, cudaFuncAttributeMaxDynamicSharedMemorySize, SM_TOTAL);
    cudaFuncSetAttribute((const void*)gemm_h<__half, 2>, cudaFuncAttributeMaxDynamicSharedMemorySize, SM_TOTAL);
    cudaFuncSetAttribute((const void*)gemm_h<float, 0>,  cudaFuncAttributeMaxDynamicSharedMemorySize, SM_TOTAL);

    const long SD = (long)Sdim * Ddim;      // 1048576
    const long SS = (long)Sdim * Sdim;      // 4194304
    const float scale = 1.0f / sqrtf((float)Ddim);
    dim3 blk(256);

    // 0) fused convert + rowsum zero (one launch, MLP=4)
    {
        PrepArgs a;
        a.x = x; a.wq = Wq; a.wk = Wk; a.wv = Wv; a.wp = Wp;
        a.hx = hx; a.hwq = hwq; a.hwk = hwk; a.hwv = hwv; a.hwp = hwp;
        a.rs = rs;
        prep_kernel<<<PREP_THREADS / 256, 256>>>(a);
    }

    // 1) fused Q-proj + K-proj + V^T-proj (one launch, 6144 CTAs)
    {
        dim3 grid(64, 1, 96);
        qkv_kernel<<<grid, blk, SM_TOTAL>>>(hx, hwq, hwk, hwv, hq, hk, hv);
    }

    // 2) logits + masked exp2 + rowsum (M=N=S,K=D); z1=b (Z2=H), z2=h
    {
        dim3 grid(Sdim / 128, Sdim / 128, Bdim * Hdim);
        gemm_h<__half, 1><<<grid, blk, SM_TOTAL>>>(hq, hk, hp, Ddim, Ddim, Ddim, Sdim,
                                                   Hdim, Hdim * SD, SD, Hdim * SD, SD,
                                                   Hdim * SS, SS,
                                                   scale * LOG2E, mask, rs);
    }

    // 3) PV with rowsum normalization (M=S,N=D,K=S) -> concat; z1=b, z2=h
    {
        dim3 grid(Ddim / 128, Sdim / 128, Bdim * Hdim);
        gemm_h<__half, 2><<<grid, blk, SM_TOTAL>>>(hp, hv, hc, Sdim, Sdim, Sdim,
                                                   Hdim * Ddim, Hdim,
                                                   (long)Hdim * SS, SS,
                                                   (long)Hdim * SD, SD,
                                                   (long)Sdim * Hdim * Ddim, (long)Ddim,
                                                   1.f, nullptr, rs);
    }

    // 4) out proj (M=S,N=D,K=H*D), z=b
    {
        dim3 grid(Ddim / 128, Sdim / 128, Bdim);
        gemm_h<float, 0><<<grid, blk, SM_TOTAL>>>(hc, hwp, out, Hdim * Ddim,
                                                  Hdim * Ddim, Hdim * Ddim, Ddim, 1,
                                                  (long)Sdim * Hdim * Ddim, 0, 0, 0,
                                                  SD, 0, 1.f, nullptr, nullptr);
    }
}